// round 1
// baseline (speedup 1.0000x reference)
#include <cuda_runtime.h>
#include <cuda_bf16.h>
#include <math.h>

// ---------------- problem constants ----------------
#define LQ   2048
#define HID  3072
#define NHEADS 24
#define HD   128
#define MLP  12288
#define H1   21504   // 3*HID + MLP  (lin1 out)
#define H2   15360   // HID + MLP    (lin2 in)

// ---------------- scratch (device globals; no allocs allowed) ----------------
__device__ float g_m[3 * HID];                       // modulation: shift|scale|gate
__device__ float g_xmod[(size_t)LQ * HID];           // modulated layernorm output
__device__ float g_h[(size_t)LQ * H1];               // lin1 output (qkv | mlp)
__device__ float g_q[(size_t)NHEADS * LQ * HD];      // head-major q (scaled by 1/sqrt(d))
__device__ float g_k[(size_t)NHEADS * LQ * HD];
__device__ float g_v[(size_t)NHEADS * LQ * HD];
__device__ float g_s[(size_t)NHEADS * LQ * LQ];      // attention scores / probs
__device__ float g_a2[(size_t)LQ * H2];              // [attn | gelu(mlp)] concat
__device__ float g_o[(size_t)LQ * HID];              // lin2 output

// ---------------- packed f32x2 helpers (B300: fma.rn.f32x2, PTX-only) ----------------
typedef unsigned long long u64;
__device__ __forceinline__ u64 pack2(float lo, float hi) {
    u64 r; asm("mov.b64 %0, {%1, %2};" : "=l"(r) : "f"(lo), "f"(hi)); return r;
}
__device__ __forceinline__ void fma2(u64& d, u64 a, u64 b) {
    asm("fma.rn.f32x2 %0, %1, %2, %0;" : "+l"(d) : "l"(a), "l"(b));
}
__device__ __forceinline__ float2 unpack2(u64 v) {
    float2 r; asm("mov.b64 {%0, %1}, %2;" : "=f"(r.x), "=f"(r.y) : "l"(v)); return r;
}

// ---------------- generic fp32 GEMM, C[M,N] = A * B(^T) + bias ----------------
// BT=true : B is [N,K] row-major (C = A * B^T)  -- "NT"
// BT=false: B is [K,N] row-major (C = A * B)    -- "NN"
// Tiles: BM=128 BN=64 BK=16, 256 threads, 8x4 outputs/thread via f32x2 FMA.
// All dims must divide the tile sizes (true for every call here).
template<bool BT>
__global__ __launch_bounds__(256)
void gemm_f32(const float* __restrict__ A, const float* __restrict__ B,
              const float* __restrict__ bias, float* __restrict__ C,
              int K, int lda, int ldb, int ldc,
              long long sA, long long sB, long long sC)
{
    constexpr int BM = 128, BN = 64, BK = 16, TM = 8;
    __shared__ float As[BK][BM + 4];   // +4 pad: 16B-aligned rows, <=2-way bank conflicts
    __shared__ float Bs[BK][BN + 4];

    A += (long long)blockIdx.z * sA;
    B += (long long)blockIdx.z * sB;
    C += (long long)blockIdx.z * sC;

    const int m0 = blockIdx.y * BM;
    const int n0 = blockIdx.x * BN;
    const int tid = threadIdx.x;
    const int tx = tid & 15;          // 16 col-groups of 4
    const int ty = tid >> 4;          // 16 row-groups of 8
    const int ar = tid >> 2;          // tile-load row
    const int ac = (tid & 3) << 2;    // tile-load k-offset (float4)

    u64 acc[TM][2];
#pragma unroll
    for (int i = 0; i < TM; i++) { acc[i][0] = 0ull; acc[i][1] = 0ull; }

    for (int k0 = 0; k0 < K; k0 += BK) {
        // load A tile (transposed into k-major smem)
#pragma unroll
        for (int i = 0; i < 2; i++) {
            int r = ar + i * 64;
            const float4 a = *(const float4*)(A + (long long)(m0 + r) * lda + (k0 + ac));
            As[ac + 0][r] = a.x; As[ac + 1][r] = a.y; As[ac + 2][r] = a.z; As[ac + 3][r] = a.w;
        }
        // load B tile
        if (BT) {
            const float4 b = *(const float4*)(B + (long long)(n0 + ar) * ldb + (k0 + ac));
            Bs[ac + 0][ar] = b.x; Bs[ac + 1][ar] = b.y; Bs[ac + 2][ar] = b.z; Bs[ac + 3][ar] = b.w;
        } else {
            int kk = tid >> 4, c = (tid & 15) << 2;
            const float4 b = *(const float4*)(B + (long long)(k0 + kk) * ldb + (n0 + c));
            *(float4*)&Bs[kk][c] = b;
        }
        __syncthreads();

#pragma unroll
        for (int kk = 0; kk < BK; kk++) {
            float4 b0 = *(const float4*)&Bs[kk][tx << 2];
            u64 bp0 = pack2(b0.x, b0.y);
            u64 bp1 = pack2(b0.z, b0.w);
            float4 a0 = *(const float4*)&As[kk][ty * TM];
            float4 a1 = *(const float4*)&As[kk][ty * TM + 4];
            float av[8] = {a0.x, a0.y, a0.z, a0.w, a1.x, a1.y, a1.z, a1.w};
#pragma unroll
            for (int i = 0; i < TM; i++) {
                u64 ap = pack2(av[i], av[i]);
                fma2(acc[i][0], ap, bp0);
                fma2(acc[i][1], ap, bp1);
            }
        }
        __syncthreads();
    }

    float4 bv = make_float4(0.f, 0.f, 0.f, 0.f);
    if (bias) bv = *(const float4*)(bias + n0 + (tx << 2));
#pragma unroll
    for (int i = 0; i < TM; i++) {
        float2 p0 = unpack2(acc[i][0]);
        float2 p1 = unpack2(acc[i][1]);
        float4 o = make_float4(p0.x + bv.x, p0.y + bv.y, p1.x + bv.z, p1.y + bv.w);
        *(float4*)(C + (long long)(m0 + ty * TM + i) * ldc + n0 + (tx << 2)) = o;
    }
}

// ---------------- modulation: m = silu(vec) @ mod_w^T + mod_b ----------------
__global__ void k_silu_mod(const float* __restrict__ vec,
                           const float* __restrict__ mod_w,
                           const float* __restrict__ mod_b)
{
    __shared__ float sv[HID];
    for (int i = threadIdx.x; i < HID; i += 256) {
        float v = vec[i];
        sv[i] = v / (1.f + expf(-v));
    }
    __syncthreads();
    int row = blockIdx.x * 8 + (threadIdx.x >> 5);
    int lane = threadIdx.x & 31;
    const float4* w4 = (const float4*)(mod_w + (long long)row * HID);
    const float4* s4 = (const float4*)sv;
    float acc = 0.f;
    for (int i = lane; i < HID / 4; i += 32) {
        float4 w = w4[i], s = s4[i];
        acc += w.x * s.x + w.y * s.y + w.z * s.z + w.w * s.w;
    }
#pragma unroll
    for (int o = 16; o; o >>= 1) acc += __shfl_xor_sync(~0u, acc, o);
    if (lane == 0) g_m[row] = acc + mod_b[row];
}

// ---------------- x_mod = (1+scale)*LN(x) + shift ----------------
__global__ void k_ln_mod(const float* __restrict__ x)
{
    __shared__ float wsum[8], wsq[8], stats[2];
    int l = blockIdx.x, tid = threadIdx.x;
    const float4* xr = (const float4*)(x + (size_t)l * HID);
    float4 v[3];
    float s = 0.f, q = 0.f;
#pragma unroll
    for (int i = 0; i < 3; i++) {
        float4 t = xr[tid + i * 256]; v[i] = t;
        s += t.x + t.y + t.z + t.w;
        q += t.x * t.x + t.y * t.y + t.z * t.z + t.w * t.w;
    }
#pragma unroll
    for (int o = 16; o; o >>= 1) {
        s += __shfl_xor_sync(~0u, s, o);
        q += __shfl_xor_sync(~0u, q, o);
    }
    if ((tid & 31) == 0) { wsum[tid >> 5] = s; wsq[tid >> 5] = q; }
    __syncthreads();
    if (tid == 0) {
        float S = 0.f, Q = 0.f;
        for (int i = 0; i < 8; i++) { S += wsum[i]; Q += wsq[i]; }
        float mu = S * (1.f / HID);
        float var = Q * (1.f / HID) - mu * mu;
        stats[0] = mu;
        stats[1] = rsqrtf(var + 1e-6f);
    }
    __syncthreads();
    float mu = stats[0], rstd = stats[1];
    float4* xo = (float4*)(g_xmod + (size_t)l * HID);
    const float4* msh = (const float4*)g_m;
    const float4* msc = (const float4*)(g_m + HID);
#pragma unroll
    for (int i = 0; i < 3; i++) {
        int c = tid + i * 256;
        float4 t = v[i], sh = msh[c], sc = msc[c];
        float4 o;
        o.x = (1.f + sc.x) * ((t.x - mu) * rstd) + sh.x;
        o.y = (1.f + sc.y) * ((t.y - mu) * rstd) + sh.y;
        o.z = (1.f + sc.z) * ((t.z - mu) * rstd) + sh.z;
        o.w = (1.f + sc.w) * ((t.w - mu) * rstd) + sh.w;
        xo[c] = o;
    }
}

// ---------------- qkv: rmsnorm(q,k) + rope + 1/sqrt(d) into head-major; v copy ----------------
__global__ void k_qkv(const float* __restrict__ pe,
                      const float* __restrict__ q_scale,
                      const float* __restrict__ k_scale)
{
    int l = blockIdx.x;
    int w = threadIdx.x >> 5, lane = threadIdx.x & 31;
    const float* hrow = g_h + (size_t)l * H1;

    for (int hd = w; hd < NHEADS; hd += 8) {
#pragma unroll
        for (int t = 0; t < 2; t++) {
            const float* src = hrow + t * HID + hd * HD;
            float4 val = *(const float4*)(src + lane * 4);
            float ssq = val.x * val.x + val.y * val.y + val.z * val.z + val.w * val.w;
#pragma unroll
            for (int o = 16; o; o >>= 1) ssq += __shfl_xor_sync(~0u, ssq, o);
            float rr = rsqrtf(ssq * (1.f / HD) + 1e-6f);
            const float* scp = (t == 0) ? q_scale : k_scale;
            float4 scv = *(const float4*)(scp + lane * 4);
            float v0 = val.x * rr * scv.x;
            float v1 = val.y * rr * scv.y;
            float v2 = val.z * rr * scv.z;
            float v3 = val.w * rr * scv.w;
            // rope: pair i -> new[2i] = pe[i,0,0]*t0 + pe[i,0,1]*t1 ; new[2i+1] = pe[i,1,0]*t0 + pe[i,1,1]*t1
            const float* pep = pe + (size_t)l * 256 + lane * 8;
            float4 peA = *(const float4*)(pep);
            float4 peB = *(const float4*)(pep + 4);
            float o0 = peA.x * v0 + peA.y * v1;
            float o1 = peA.z * v0 + peA.w * v1;
            float o2 = peB.x * v2 + peB.y * v3;
            float o3 = peB.z * v2 + peB.w * v3;
            float s = (t == 0) ? 0.08838834764831845f : 1.0f;  // fold 1/sqrt(128) into q
            float4 outv = make_float4(o0 * s, o1 * s, o2 * s, o3 * s);
            float* dst = ((t == 0) ? g_q : g_k) + ((size_t)hd * LQ + l) * HD + lane * 4;
            *(float4*)dst = outv;
        }
    }
    // v: straight copy into head-major layout
    for (int j = threadIdx.x; j < HID / 4; j += 256) {
        int e = j * 4;
        int hd = e >> 7, d = e & 127;
        float4 t = *(const float4*)(hrow + 2 * HID + e);
        *(float4*)(g_v + ((size_t)hd * LQ + l) * HD + d) = t;
    }
}

// ---------------- row softmax over scores ----------------
__global__ void k_softmax()
{
    __shared__ float wred[8];
    size_t row = blockIdx.x;
    float4* p = (float4*)(g_s + row * (size_t)LQ);
    int tid = threadIdx.x;
    float4 v[2];
    float mx = -1e30f;
#pragma unroll
    for (int i = 0; i < 2; i++) {
        float4 t = p[tid + i * 256]; v[i] = t;
        mx = fmaxf(mx, fmaxf(fmaxf(t.x, t.y), fmaxf(t.z, t.w)));
    }
#pragma unroll
    for (int o = 16; o; o >>= 1) mx = fmaxf(mx, __shfl_xor_sync(~0u, mx, o));
    if ((tid & 31) == 0) wred[tid >> 5] = mx;
    __syncthreads();
    mx = wred[0];
#pragma unroll
    for (int i = 1; i < 8; i++) mx = fmaxf(mx, wred[i]);
    __syncthreads();   // protect wred reuse
    float s = 0.f;
#pragma unroll
    for (int i = 0; i < 2; i++) {
        v[i].x = __expf(v[i].x - mx);
        v[i].y = __expf(v[i].y - mx);
        v[i].z = __expf(v[i].z - mx);
        v[i].w = __expf(v[i].w - mx);
        s += v[i].x + v[i].y + v[i].z + v[i].w;
    }
#pragma unroll
    for (int o = 16; o; o >>= 1) s += __shfl_xor_sync(~0u, s, o);
    if ((tid & 31) == 0) wred[tid >> 5] = s;
    __syncthreads();
    s = 0.f;
#pragma unroll
    for (int i = 0; i < 8; i++) s += wred[i];
    float inv = 1.f / s;
#pragma unroll
    for (int i = 0; i < 2; i++) {
        v[i].x *= inv; v[i].y *= inv; v[i].z *= inv; v[i].w *= inv;
        p[tid + i * 256] = v[i];
    }
}

// ---------------- gelu(mlp) -> a2[:, HID:] ----------------
__device__ __forceinline__ float gelu_t(float x)
{
    float u = 0.7978845608028654f * (x + 0.044715f * x * x * x);
    return 0.5f * x * (1.f + tanhf(u));
}
__global__ void k_gelu()
{
    size_t f = (size_t)blockIdx.x * 256 + threadIdx.x;   // float4 index, total L*MLP/4
    size_t e = f * 4;
    size_t l = e / MLP;
    int j = (int)(e % MLP);
    float4 t = *(const float4*)(g_h + l * H1 + 3 * HID + j);
    float4 o = make_float4(gelu_t(t.x), gelu_t(t.y), gelu_t(t.z), gelu_t(t.w));
    *(float4*)(g_a2 + l * H2 + HID + j) = o;
}

// ---------------- out = x + gate * lin2out ----------------
__global__ void k_final(const float* __restrict__ x, float* __restrict__ out)
{
    size_t f = (size_t)blockIdx.x * 256 + threadIdx.x;   // float4 index, total L*HID/4
    size_t e = f * 4;
    int c = (int)(e % HID);
    float4 xv = ((const float4*)x)[f];
    float4 ov = ((const float4*)g_o)[f];
    float4 gv = *(const float4*)(g_m + 2 * HID + c);
    float4 o = make_float4(xv.x + gv.x * ov.x, xv.y + gv.y * ov.y,
                           xv.z + gv.z * ov.z, xv.w + gv.w * ov.w);
    ((float4*)out)[f] = o;
}

// ---------------- launch ----------------
extern "C" void kernel_launch(void* const* d_in, const int* in_sizes, int n_in,
                              void* d_out, int out_size)
{
    (void)in_sizes; (void)n_in; (void)out_size;
    const float* x      = (const float*)d_in[0];
    const float* vec    = (const float*)d_in[1];
    const float* pe     = (const float*)d_in[2];
    const float* mod_w  = (const float*)d_in[3];
    const float* mod_b  = (const float*)d_in[4];
    const float* lin1_w = (const float*)d_in[5];
    const float* lin1_b = (const float*)d_in[6];
    const float* lin2_w = (const float*)d_in[7];
    const float* lin2_b = (const float*)d_in[8];
    const float* q_scale = (const float*)d_in[9];
    const float* k_scale = (const float*)d_in[10];
    float* out = (float*)d_out;

    float *p_xmod, *p_h, *p_q, *p_k, *p_v, *p_s, *p_a2, *p_o;
    cudaGetSymbolAddress((void**)&p_xmod, g_xmod);
    cudaGetSymbolAddress((void**)&p_h, g_h);
    cudaGetSymbolAddress((void**)&p_q, g_q);
    cudaGetSymbolAddress((void**)&p_k, g_k);
    cudaGetSymbolAddress((void**)&p_v, g_v);
    cudaGetSymbolAddress((void**)&p_s, g_s);
    cudaGetSymbolAddress((void**)&p_a2, g_a2);
    cudaGetSymbolAddress((void**)&p_o, g_o);

    // 1) modulation GEMV
    k_silu_mod<<<(3 * HID) / 8, 256>>>(vec, mod_w, mod_b);
    // 2) layernorm + modulate
    k_ln_mod<<<LQ, 256>>>(x);
    // 3) lin1: h = x_mod @ lin1_w^T + lin1_b   (M=2048, K=3072, N=21504)
    gemm_f32<true><<<dim3(H1 / 64, LQ / 128, 1), 256>>>(
        p_xmod, lin1_w, lin1_b, p_h, HID, HID, HID, H1, 0, 0, 0);
    // 4) qkv prep (rmsnorm + rope + scale, head-major)
    k_qkv<<<LQ, 256>>>(pe, q_scale, k_scale);
    // 5) scores = q @ k^T (batched over heads)   (M=N=2048, K=128)
    gemm_f32<true><<<dim3(LQ / 64, LQ / 128, NHEADS), 256>>>(
        p_q, p_k, nullptr, p_s, HD, HD, HD, LQ,
        (long long)LQ * HD, (long long)LQ * HD, (long long)LQ * LQ);
    // 6) softmax rows
    k_softmax<<<NHEADS * LQ, 256>>>();
    // 7) attn = P @ v, written into a2[:, h*128:(h+1)*128]   (M=2048, N=128, K=2048)
    gemm_f32<false><<<dim3(HD / 64, LQ / 128, NHEADS), 256>>>(
        p_s, p_v, nullptr, p_a2, LQ, LQ, HD, H2,
        (long long)LQ * LQ, (long long)LQ * HD, (long long)HD);
    // 8) gelu(mlp) -> a2[:, HID:]
    k_gelu<<<(LQ * MLP / 4) / 256, 256>>>();
    // 9) lin2: o = a2 @ lin2_w^T + lin2_b   (M=2048, K=15360, N=3072)
    gemm_f32<true><<<dim3(HID / 64, LQ / 128, 1), 256>>>(
        p_a2, lin2_w, lin2_b, p_o, H2, H2, H2, HID, 0, 0, 0);
    // 10) out = x + gate * o
    k_final<<<(LQ * HID / 4) / 256, 256>>>(x, out);
}

// round 5
// speedup vs baseline: 1.5570x; 1.5570x over previous
#include <cuda_runtime.h>
#include <cuda_bf16.h>
#include <math.h>
#include <stdint.h>

// ---------------- problem constants ----------------
#define LQ   2048
#define HID  3072
#define NHEADS 24
#define HD   128
#define MLP  12288
#define H1   21504   // 3*HID + MLP  (lin1 out)
#define H2   15360   // HID + MLP    (lin2 in)
#define K1S  (3*HID)     // 9216  lin1 split-K
#define K2S  (3*H2)      // 46080 lin2 split-K
#define KQS  (3*HD)      // 384   scores split-K
#define KPV  (3*LQ)      // 6144  attn P*V split-K

// ---------------- scratch (device globals; no allocs allowed) ----------------
__device__ float g_m[3 * HID];                                   // shift|scale|gate
__device__ __nv_bfloat16 g_a1s[(size_t)LQ * K1S];                // split xmod
__device__ __nv_bfloat16 g_w1s[(size_t)H1 * K1S];                // split lin1_w
__device__ __nv_bfloat16 g_w2s[(size_t)HID * K2S];               // split lin2_w
__device__ float g_h[(size_t)LQ * H1];                           // lin1 out fp32
__device__ __nv_bfloat16 g_qs[(size_t)NHEADS * LQ * KQS];        // split q (scaled)
__device__ __nv_bfloat16 g_ks[(size_t)NHEADS * LQ * KQS];        // split k
__device__ __nv_bfloat16 g_vts[(size_t)NHEADS * HD * KPV];       // split v^T  [Vh|Vl|Vh]
__device__ float g_s[(size_t)NHEADS * LQ * LQ];                  // scores fp32
__device__ __nv_bfloat16 g_ps[(size_t)NHEADS * LQ * KPV];        // split probs [Ph|Ph|Pl]
__device__ __nv_bfloat16 g_a2s[(size_t)LQ * K2S];                // split [attn|gelu]
__device__ float g_o[(size_t)LQ * HID];                          // lin2 out

// ---------------- helpers ----------------
__device__ __forceinline__ uint32_t smem_u32(const void* p) {
    uint32_t a;
    asm("{ .reg .u64 t; cvta.to.shared.u64 t, %1; cvt.u32.u64 %0, t; }" : "=r"(a) : "l"(p));
    return a;
}
__device__ __forceinline__ void ldsm4(uint32_t* r, uint32_t addr) {
    asm volatile("ldmatrix.sync.aligned.m8n8.x4.shared.b16 {%0,%1,%2,%3}, [%4];"
        : "=r"(r[0]), "=r"(r[1]), "=r"(r[2]), "=r"(r[3]) : "r"(addr));
}
__device__ __forceinline__ void mma16816(float* d, const uint32_t* a, uint32_t b0, uint32_t b1) {
    asm volatile("mma.sync.aligned.m16n8k16.row.col.f32.bf16.bf16.f32 "
        "{%0,%1,%2,%3}, {%4,%5,%6,%7}, {%8,%9}, {%0,%1,%2,%3};"
        : "+f"(d[0]), "+f"(d[1]), "+f"(d[2]), "+f"(d[3])
        : "r"(a[0]), "r"(a[1]), "r"(a[2]), "r"(a[3]), "r"(b0), "r"(b1));
}
__device__ __forceinline__ uint32_t bf2u(__nv_bfloat16 a, __nv_bfloat16 b) {
    __nv_bfloat162 t(a, b);
    return *(uint32_t*)&t;
}
__device__ __forceinline__ void split1(float v, __nv_bfloat16& hi, __nv_bfloat16& lo) {
    hi = __float2bfloat16(v);
    lo = __float2bfloat16(v - __bfloat162float(hi));
}

// ================= mma.sync bf16 NT GEMM =================
// C[m,n] = sum_k A[m,k]*B[n,k] (+bias). BM=BN=128, BK=32, 256 thr (8 warps 2x4).
// grid (N/128, M/128, batch), x fastest so a wave shares one A m-panel in L2.
// EPI 0: fp32 out (+bias). EPI 1: split3 bf16 into a2s attn columns.
template<int EPI>
__global__ __launch_bounds__(256)
void gemm_mma(const __nv_bfloat16* __restrict__ A, const __nv_bfloat16* __restrict__ B,
              const float* __restrict__ bias, void* __restrict__ Cv,
              int K, int lda, int ldb, int ldc,
              long long sA, long long sB, long long sC)
{
    __shared__ __nv_bfloat16 As[2][128][40];   // 40-col pad: 80B row stride, LDSM conflict-free
    __shared__ __nv_bfloat16 Bs[2][128][40];

    const int tid = threadIdx.x, lane = tid & 31, w = tid >> 5;
    const int wm = w >> 2, wn = w & 3;

    A += (long long)blockIdx.z * sA + (long long)(blockIdx.y * 128) * lda;
    B += (long long)blockIdx.z * sB + (long long)(blockIdx.x * 128) * ldb;

    // staging: each thread owns 32B (two uint4) of one row per tile
    const int srow = tid >> 1;
    const int scg  = (tid & 1) * 16;             // bf16 offset: 0 or 16
    const __nv_bfloat16* pA = A + (long long)srow * lda + scg;
    const __nv_bfloat16* pB = B + (long long)srow * ldb + scg;

    const uint32_t aBase = smem_u32(&As[0][0][0]);
    const uint32_t bBase = smem_u32(&Bs[0][0][0]);
    // ldmatrix byte offsets (row stride = 80B)
    const uint32_t aOff = (uint32_t)((wm * 64 + (lane & 15)) * 80 + (lane >> 4) * 16);
    const uint32_t bOff = (uint32_t)((wn * 32 + (lane & 7) + ((lane >> 4) << 3)) * 80
                                     + ((lane >> 3) & 1) * 16);
    const uint32_t sStore = (uint32_t)(srow * 80 + scg * 2);

    float d[4][4][4];
#pragma unroll
    for (int i = 0; i < 4; i++)
#pragma unroll
        for (int j = 0; j < 4; j++) {
            d[i][j][0] = 0.f; d[i][j][1] = 0.f; d[i][j][2] = 0.f; d[i][j][3] = 0.f;
        }

    const int NKB = K >> 5;
    // preload k-tile 0
    {
        uint4 a0 = *(const uint4*)(pA);
        uint4 a1 = *(const uint4*)(pA + 8);
        uint4 b0 = *(const uint4*)(pB);
        uint4 b1 = *(const uint4*)(pB + 8);
        *(uint4*)((char*)As + sStore) = a0;
        *(uint4*)((char*)As + sStore + 16) = a1;
        *(uint4*)((char*)Bs + sStore) = b0;
        *(uint4*)((char*)Bs + sStore + 16) = b1;
    }
    __syncthreads();

    for (int kb = 0; kb < NKB; kb++) {
        const int buf = kb & 1;
        uint4 na0, na1, nb0, nb1;
        const bool more = (kb + 1 < NKB);
        if (more) {
            const __nv_bfloat16* qA = pA + (long long)(kb + 1) * 32;
            const __nv_bfloat16* qB = pB + (long long)(kb + 1) * 32;
            na0 = *(const uint4*)(qA);      na1 = *(const uint4*)(qA + 8);
            nb0 = *(const uint4*)(qB);      nb1 = *(const uint4*)(qB + 8);
        }
        const uint32_t aB = aBase + buf * 10240 + aOff;
        const uint32_t bB = bBase + buf * 10240 + bOff;
#pragma unroll
        for (int kk = 0; kk < 2; kk++) {
            uint32_t a[4][4], b[2][4];
#pragma unroll
            for (int i = 0; i < 4; i++) ldsm4(a[i], aB + i * 1280 + kk * 32);
#pragma unroll
            for (int j = 0; j < 2; j++) ldsm4(b[j], bB + j * 1280 + kk * 32);
#pragma unroll
            for (int i = 0; i < 4; i++) {
#pragma unroll
                for (int j = 0; j < 2; j++) {
                    mma16816(d[i][2 * j],     a[i], b[j][0], b[j][1]);
                    mma16816(d[i][2 * j + 1], a[i], b[j][2], b[j][3]);
                }
            }
        }
        if (more) {
            const uint32_t dst = (buf ^ 1) * 10240 + sStore;
            *(uint4*)((char*)As + dst) = na0;
            *(uint4*)((char*)As + dst + 16) = na1;
            *(uint4*)((char*)Bs + dst) = nb0;
            *(uint4*)((char*)Bs + dst + 16) = nb1;
        }
        __syncthreads();
    }

    // ---------------- epilogue ----------------
    const int mBase = blockIdx.y * 128 + wm * 64 + (lane >> 2);
    const int nBase = blockIdx.x * 128 + wn * 32 + (lane & 3) * 2;
    if (EPI == 0) {
        float* C = (float*)Cv + (long long)blockIdx.z * sC;
#pragma unroll
        for (int i = 0; i < 4; i++) {
#pragma unroll
            for (int j = 0; j < 4; j++) {
                const int row = mBase + i * 16;
                const int col = nBase + j * 8;
                float b0 = 0.f, b1 = 0.f;
                if (bias) { b0 = bias[col]; b1 = bias[col + 1]; }
                *(float2*)(C + (long long)row * ldc + col) =
                    make_float2(d[i][j][0] + b0, d[i][j][1] + b1);
                *(float2*)(C + (long long)(row + 8) * ldc + col) =
                    make_float2(d[i][j][2] + b0, d[i][j][3] + b1);
            }
        }
    } else {
        __nv_bfloat16* C = (__nv_bfloat16*)Cv + (long long)blockIdx.z * sC;
#pragma unroll
        for (int i = 0; i < 4; i++) {
#pragma unroll
            for (int j = 0; j < 4; j++) {
#pragma unroll
                for (int h = 0; h < 2; h++) {
                    const int row = mBase + i * 16 + 8 * h;
                    const int col = nBase + j * 8;
                    float v0 = d[i][j][2 * h], v1 = d[i][j][2 * h + 1];
                    __nv_bfloat16 h0, l0, h1, l1;
                    split1(v0, h0, l0);
                    split1(v1, h1, l1);
                    uint32_t hh = bf2u(h0, h1), ll = bf2u(l0, l1);
                    __nv_bfloat16* p = C + (long long)row * ldc + col;
                    *(uint32_t*)(p)          = hh;   // A pattern: [Ah|Ah|Al]
                    *(uint32_t*)(p + H2)     = hh;
                    *(uint32_t*)(p + 2 * H2) = ll;
                }
            }
        }
    }
}

// ---------------- weight split: w[N,Kc] fp32 -> [Bh|Bl|Bh] bf16 [N,3Kc] ----------------
__global__ void k_wsplit(const float* __restrict__ w, __nv_bfloat16* __restrict__ ws, int Kc)
{
    size_t f = (size_t)blockIdx.x * 256 + threadIdx.x;
    size_t e = f * 4;
    size_t n = e / Kc;
    int k = (int)(e % Kc);
    float4 v = *(const float4*)(w + e);
    __nv_bfloat16 h0,l0,h1,l1,h2,l2,h3,l3;
    split1(v.x,h0,l0); split1(v.y,h1,l1); split1(v.z,h2,l2); split1(v.w,h3,l3);
    uint2 hi = make_uint2(bf2u(h0,h1), bf2u(h2,h3));
    uint2 lo = make_uint2(bf2u(l0,l1), bf2u(l2,l3));
    __nv_bfloat16* row = ws + n * (size_t)(3 * Kc);
    *(uint2*)(row + k)          = hi;
    *(uint2*)(row + Kc + k)     = lo;
    *(uint2*)(row + 2 * Kc + k) = hi;
}

// ---------------- modulation GEMV ----------------
__global__ void k_silu_mod(const float* __restrict__ vec,
                           const float* __restrict__ mod_w,
                           const float* __restrict__ mod_b)
{
    __shared__ float sv[HID];
    for (int i = threadIdx.x; i < HID; i += 256) {
        float v = vec[i];
        sv[i] = v / (1.f + expf(-v));
    }
    __syncthreads();
    int row = blockIdx.x * 8 + (threadIdx.x >> 5);
    int lane = threadIdx.x & 31;
    const float4* w4 = (const float4*)(mod_w + (long long)row * HID);
    const float4* s4 = (const float4*)sv;
    float acc = 0.f;
    for (int i = lane; i < HID / 4; i += 32) {
        float4 w = w4[i], s = s4[i];
        acc += w.x * s.x + w.y * s.y + w.z * s.z + w.w * s.w;
    }
#pragma unroll
    for (int o = 16; o; o >>= 1) acc += __shfl_xor_sync(~0u, acc, o);
    if (lane == 0) g_m[row] = acc + mod_b[row];
}

// ---------------- x_mod = (1+scale)*LN(x)+shift -> split bf16 a1s ----------------
__global__ void k_ln_mod(const float* __restrict__ x)
{
    __shared__ float wsum[8], wsq[8], stats[2];
    int l = blockIdx.x, tid = threadIdx.x;
    const float4* xr = (const float4*)(x + (size_t)l * HID);
    float4 v[3];
    float s = 0.f, q = 0.f;
#pragma unroll
    for (int i = 0; i < 3; i++) {
        float4 t = xr[tid + i * 256]; v[i] = t;
        s += t.x + t.y + t.z + t.w;
        q += t.x * t.x + t.y * t.y + t.z * t.z + t.w * t.w;
    }
#pragma unroll
    for (int o = 16; o; o >>= 1) {
        s += __shfl_xor_sync(~0u, s, o);
        q += __shfl_xor_sync(~0u, q, o);
    }
    if ((tid & 31) == 0) { wsum[tid >> 5] = s; wsq[tid >> 5] = q; }
    __syncthreads();
    if (tid == 0) {
        float S = 0.f, Q = 0.f;
        for (int i = 0; i < 8; i++) { S += wsum[i]; Q += wsq[i]; }
        float mu = S * (1.f / HID);
        float var = Q * (1.f / HID) - mu * mu;
        stats[0] = mu;
        stats[1] = rsqrtf(var + 1e-6f);
    }
    __syncthreads();
    float mu = stats[0], rstd = stats[1];
    __nv_bfloat16* orow = g_a1s + (size_t)l * K1S;
    const float4* msh = (const float4*)g_m;
    const float4* msc = (const float4*)(g_m + HID);
#pragma unroll
    for (int i = 0; i < 3; i++) {
        int c = tid + i * 256;
        float4 t = v[i], sh = msh[c], sc = msc[c];
        float o0 = (1.f + sc.x) * ((t.x - mu) * rstd) + sh.x;
        float o1 = (1.f + sc.y) * ((t.y - mu) * rstd) + sh.y;
        float o2 = (1.f + sc.z) * ((t.z - mu) * rstd) + sh.z;
        float o3 = (1.f + sc.w) * ((t.w - mu) * rstd) + sh.w;
        __nv_bfloat16 h0,l0,h1,l1,h2,l2,h3,l3;
        split1(o0,h0,l0); split1(o1,h1,l1); split1(o2,h2,l2); split1(o3,h3,l3);
        uint2 hi = make_uint2(bf2u(h0,h1), bf2u(h2,h3));
        uint2 lo = make_uint2(bf2u(l0,l1), bf2u(l2,l3));
        *(uint2*)(orow + c * 4)            = hi;   // A pattern: [Ah|Ah|Al]
        *(uint2*)(orow + HID + c * 4)      = hi;
        *(uint2*)(orow + 2 * HID + c * 4)  = lo;
    }
}

// ---------------- qkv prep: rmsnorm + rope + split (head-major) ----------------
__global__ void k_qkv(const float* __restrict__ pe,
                      const float* __restrict__ q_scale,
                      const float* __restrict__ k_scale)
{
    int l = blockIdx.x;
    int w = threadIdx.x >> 5, lane = threadIdx.x & 31;
    const float* hrow = g_h + (size_t)l * H1;

    for (int hd = w; hd < NHEADS; hd += 8) {
#pragma unroll
        for (int t = 0; t < 2; t++) {
            const float* src = hrow + t * HID + hd * HD;
            float4 val = *(const float4*)(src + lane * 4);
            float ssq = val.x * val.x + val.y * val.y + val.z * val.z + val.w * val.w;
#pragma unroll
            for (int o = 16; o; o >>= 1) ssq += __shfl_xor_sync(~0u, ssq, o);
            float rr = rsqrtf(ssq * (1.f / HD) + 1e-6f);
            const float* scp = (t == 0) ? q_scale : k_scale;
            float4 scv = *(const float4*)(scp + lane * 4);
            float v0 = val.x * rr * scv.x;
            float v1 = val.y * rr * scv.y;
            float v2 = val.z * rr * scv.z;
            float v3 = val.w * rr * scv.w;
            const float* pep = pe + (size_t)l * 256 + lane * 8;
            float4 peA = *(const float4*)(pep);
            float4 peB = *(const float4*)(pep + 4);
            float o0 = peA.x * v0 + peA.y * v1;
            float o1 = peA.z * v0 + peA.w * v1;
            float o2 = peB.x * v2 + peB.y * v3;
            float o3 = peB.z * v2 + peB.w * v3;
            float s = (t == 0) ? 0.08838834764831845f : 1.0f;  // fold 1/sqrt(128) into q
            o0 *= s; o1 *= s; o2 *= s; o3 *= s;
            __nv_bfloat16 h0,l0b,h1,l1b,h2,l2b,h3,l3b;
            split1(o0,h0,l0b); split1(o1,h1,l1b); split1(o2,h2,l2b); split1(o3,h3,l3b);
            uint2 hi = make_uint2(bf2u(h0,h1), bf2u(h2,h3));
            uint2 lo = make_uint2(bf2u(l0b,l1b), bf2u(l2b,l3b));
            __nv_bfloat16* dst = ((t == 0) ? g_qs : g_ks) + ((size_t)hd * LQ + l) * KQS + lane * 4;
            *(uint2*)(dst) = hi;
            if (t == 0) {           // q = A side: [Ah|Ah|Al]
                *(uint2*)(dst + HD)     = hi;
                *(uint2*)(dst + 2*HD)   = lo;
            } else {                // k = B side: [Bh|Bl|Bh]
                *(uint2*)(dst + HD)     = lo;
                *(uint2*)(dst + 2*HD)   = hi;
            }
        }
    }
}

// ---------------- v transpose+split: g_h v cols -> vts [h][d][Vh|Vl|Vh] ----------------
__global__ void k_vt()
{
    __shared__ float t[32][33];
    int h = blockIdx.z;
    int l0 = blockIdx.x * 32, d0 = blockIdx.y * 32;
    int tx = threadIdx.x & 31, ty = threadIdx.x >> 5;  // 32x8
#pragma unroll
    for (int k = 0; k < 4; k++)
        t[ty + 8 * k][tx] = g_h[(size_t)(l0 + ty + 8 * k) * H1 + 2 * HID + h * HD + d0 + tx];
    __syncthreads();
#pragma unroll
    for (int k = 0; k < 4; k++) {
        float v = t[tx][ty + 8 * k];
        __nv_bfloat16 hi, lo;
        split1(v, hi, lo);
        size_t base = ((size_t)h * HD + d0 + ty + 8 * k) * KPV + l0 + tx;
        g_vts[base]          = hi;   // B pattern: [Bh|Bl|Bh]
        g_vts[base + LQ]     = lo;
        g_vts[base + 2 * LQ] = hi;
    }
}

// ---------------- softmax: g_s fp32 -> g_ps split bf16 [Ph|Ph|Pl] ----------------
__global__ void k_softmax()
{
    __shared__ float wred[8];
    size_t row = blockIdx.x;
    const float4* p = (const float4*)(g_s + row * (size_t)LQ);
    __nv_bfloat16* po = g_ps + row * (size_t)KPV;
    int tid = threadIdx.x;
    float4 v[2];
    float mx = -1e30f;
#pragma unroll
    for (int i = 0; i < 2; i++) {
        float4 t = p[tid + i * 256]; v[i] = t;
        mx = fmaxf(mx, fmaxf(fmaxf(t.x, t.y), fmaxf(t.z, t.w)));
    }
#pragma unroll
    for (int o = 16; o; o >>= 1) mx = fmaxf(mx, __shfl_xor_sync(~0u, mx, o));
    if ((tid & 31) == 0) wred[tid >> 5] = mx;
    __syncthreads();
    mx = wred[0];
#pragma unroll
    for (int i = 1; i < 8; i++) mx = fmaxf(mx, wred[i]);
    __syncthreads();
    float s = 0.f;
#pragma unroll
    for (int i = 0; i < 2; i++) {
        v[i].x = __expf(v[i].x - mx);
        v[i].y = __expf(v[i].y - mx);
        v[i].z = __expf(v[i].z - mx);
        v[i].w = __expf(v[i].w - mx);
        s += v[i].x + v[i].y + v[i].z + v[i].w;
    }
#pragma unroll
    for (int o = 16; o; o >>= 1) s += __shfl_xor_sync(~0u, s, o);
    if ((tid & 31) == 0) wred[tid >> 5] = s;
    __syncthreads();
    s = 0.f;
#pragma unroll
    for (int i = 0; i < 8; i++) s += wred[i];
    float inv = 1.f / s;
#pragma unroll
    for (int i = 0; i < 2; i++) {
        int c = (tid + i * 256) * 4;
        float p0 = v[i].x * inv, p1 = v[i].y * inv, p2 = v[i].z * inv, p3 = v[i].w * inv;
        __nv_bfloat16 h0,l0,h1,l1,h2,l2,h3,l3;
        split1(p0,h0,l0); split1(p1,h1,l1); split1(p2,h2,l2); split1(p3,h3,l3);
        uint2 hi = make_uint2(bf2u(h0,h1), bf2u(h2,h3));
        uint2 lo = make_uint2(bf2u(l0,l1), bf2u(l2,l3));
        *(uint2*)(po + c)            = hi;   // A pattern: [Ph|Ph|Pl]
        *(uint2*)(po + LQ + c)       = hi;
        *(uint2*)(po + 2 * LQ + c)   = lo;
    }
}

// ---------------- gelu(mlp) -> a2s split ----------------
__device__ __forceinline__ float gelu_t(float x)
{
    float u = 0.7978845608028654f * (x + 0.044715f * x * x * x);
    return 0.5f * x * (1.f + tanhf(u));
}
__global__ void k_gelu()
{
    size_t f = (size_t)blockIdx.x * 256 + threadIdx.x;
    size_t e = f * 4;
    size_t l = e / MLP;
    int j = (int)(e % MLP);
    float4 t = *(const float4*)(g_h + l * H1 + 3 * HID + j);
    float g0 = gelu_t(t.x), g1 = gelu_t(t.y), g2 = gelu_t(t.z), g3 = gelu_t(t.w);
    __nv_bfloat16 h0,l0,h1,l1,h2,l2,h3,l3;
    split1(g0,h0,l0); split1(g1,h1,l1); split1(g2,h2,l2); split1(g3,h3,l3);
    uint2 hi = make_uint2(bf2u(h0,h1), bf2u(h2,h3));
    uint2 lo = make_uint2(bf2u(l0,l1), bf2u(l2,l3));
    __nv_bfloat16* row = g_a2s + l * (size_t)K2S;
    *(uint2*)(row + HID + j)            = hi;   // A pattern: [Ah|Ah|Al]
    *(uint2*)(row + H2 + HID + j)       = hi;
    *(uint2*)(row + 2 * H2 + HID + j)   = lo;
}

// ---------------- out = x + gate * lin2out ----------------
__global__ void k_final(const float* __restrict__ x, float* __restrict__ out)
{
    size_t f = (size_t)blockIdx.x * 256 + threadIdx.x;
    size_t e = f * 4;
    int c = (int)(e % HID);
    float4 xv = ((const float4*)x)[f];
    float4 ov = ((const float4*)g_o)[f];
    float4 gv = *(const float4*)(g_m + 2 * HID + c);
    float4 o = make_float4(xv.x + gv.x * ov.x, xv.y + gv.y * ov.y,
                           xv.z + gv.z * ov.z, xv.w + gv.w * ov.w);
    ((float4*)out)[f] = o;
}

// ---------------- launch ----------------
extern "C" void kernel_launch(void* const* d_in, const int* in_sizes, int n_in,
                              void* d_out, int out_size)
{
    (void)in_sizes; (void)n_in; (void)out_size;
    const float* x      = (const float*)d_in[0];
    const float* vec    = (const float*)d_in[1];
    const float* pe     = (const float*)d_in[2];
    const float* mod_w  = (const float*)d_in[3];
    const float* mod_b  = (const float*)d_in[4];
    const float* lin1_w = (const float*)d_in[5];
    const float* lin1_b = (const float*)d_in[6];
    const float* lin2_w = (const float*)d_in[7];
    const float* lin2_b = (const float*)d_in[8];
    const float* q_scale = (const float*)d_in[9];
    const float* k_scale = (const float*)d_in[10];
    float* out = (float*)d_out;

    __nv_bfloat16 *p_a1s, *p_w1s, *p_w2s, *p_qs, *p_ks, *p_vts, *p_ps, *p_a2s;
    float *p_h, *p_s, *p_o;
    cudaGetSymbolAddress((void**)&p_a1s, g_a1s);
    cudaGetSymbolAddress((void**)&p_w1s, g_w1s);
    cudaGetSymbolAddress((void**)&p_w2s, g_w2s);
    cudaGetSymbolAddress((void**)&p_qs, g_qs);
    cudaGetSymbolAddress((void**)&p_ks, g_ks);
    cudaGetSymbolAddress((void**)&p_vts, g_vts);
    cudaGetSymbolAddress((void**)&p_ps, g_ps);
    cudaGetSymbolAddress((void**)&p_a2s, g_a2s);
    cudaGetSymbolAddress((void**)&p_h, g_h);
    cudaGetSymbolAddress((void**)&p_s, g_s);
    cudaGetSymbolAddress((void**)&p_o, g_o);

    // 1) modulation GEMV + weight splits + layernorm split
    k_silu_mod<<<(3 * HID) / 8, 256>>>(vec, mod_w, mod_b);
    k_wsplit<<<(int)(((size_t)H1 * HID / 4) / 256), 256>>>(lin1_w, p_w1s, HID);
    k_wsplit<<<(int)(((size_t)HID * H2 / 4) / 256), 256>>>(lin2_w, p_w2s, H2);
    k_ln_mod<<<LQ, 256>>>(x);
    // 2) lin1: h = a1s @ w1s^T + b   (M=2048, N=21504, K'=9216)
    gemm_mma<0><<<dim3(H1 / 128, LQ / 128, 1), 256>>>(
        p_a1s, p_w1s, lin1_b, p_h, K1S, K1S, K1S, H1, 0, 0, 0);
    // 3) qkv prep + v transpose/split
    k_qkv<<<LQ, 256>>>(pe, q_scale, k_scale);
    k_vt<<<dim3(LQ / 32, HD / 32, NHEADS), 256>>>();
    // 4) scores = qs @ ks^T   (M=N=2048, K'=384, batched over heads)
    gemm_mma<0><<<dim3(LQ / 128, LQ / 128, NHEADS), 256>>>(
        p_qs, p_ks, nullptr, p_s, KQS, KQS, KQS, LQ,
        (long long)LQ * KQS, (long long)LQ * KQS, (long long)LQ * LQ);
    // 5) softmax -> split bf16 probs
    k_softmax<<<NHEADS * LQ, 256>>>();
    // 6) attn = Ps @ Vts^T -> split3 into a2s cols [h*128..)   (M=2048, N=128, K'=6144)
    gemm_mma<1><<<dim3(HD / 128, LQ / 128, NHEADS), 256>>>(
        p_ps, p_vts, nullptr, p_a2s, KPV, KPV, KPV, K2S,
        (long long)LQ * KPV, (long long)HD * KPV, (long long)HD);
    // 7) gelu(mlp) -> a2s split
    k_gelu<<<(int)(((size_t)LQ * MLP / 4) / 256), 256>>>();
    // 8) lin2: o = a2s @ w2s^T + b   (M=2048, N=3072, K'=46080)
    gemm_mma<0><<<dim3(HID / 128, LQ / 128, 1), 256>>>(
        p_a2s, p_w2s, lin2_b, p_o, K2S, K2S, K2S, HID, 0, 0, 0);
    // 9) out = x + gate * o
    k_final<<<(LQ * HID / 4) / 256, 256>>>(x, out);
}